// round 1
// baseline (speedup 1.0000x reference)
#include <cuda_runtime.h>

#define BATCH 64
#define GM 5184            // 64*81 patches
#define KTOT 16384         // 256*8*8
#define NODES 1296
#define NC 43
#define OD 16
#define CO 688             // 43*16

// ---------------- scratch (static device globals; zero-initialized) ----------
__device__ float g_h[BATCH*256*24*24];        // conv1 output
__device__ float g_p[GM*128];                 // prim conv output [m][oc]
__device__ float g_u[BATCH*NODES*8];          // squashed prim caps
__device__ float g_pr[57065472];              // priors [b][n][c][o] (228MB)
__device__ float g_lg[BATCH*NODES*NC];        // routing logits
__device__ float g_s[BATCH*CO];               // routing sum (zeroed by sqout)
__device__ float g_o[BATCH*CO];               // routing outputs

// ---------------- f32x2 helpers ---------------------------------------------
__device__ __forceinline__ unsigned long long pk2(float v) {
    unsigned long long r; unsigned u = __float_as_uint(v);
    asm("mov.b64 %0, {%1, %1};" : "=l"(r) : "r"(u));
    return r;
}
__device__ __forceinline__ void fma2(unsigned long long& d,
                                     unsigned long long a, unsigned long long b) {
    asm("fma.rn.f32x2 %0, %1, %2, %0;" : "+l"(d) : "l"(a), "l"(b));
}

// ---------------- conv1 + relu ----------------------------------------------
// grid (64 batch, 128 oc-pairs), block 288 = 2 halves x 144 threads.
// Whole input image (3x32x32) in smem; each thread computes 4 outputs in a row.
__global__ void __launch_bounds__(288) conv1_k(const float* __restrict__ x,
                                               const float* __restrict__ w,
                                               const float* __restrict__ bias) {
    __shared__ float xs[3072];
    __shared__ float ws[2][243];
    int b = blockIdx.x, oc0 = blockIdx.y, t = threadIdx.x;
    const float* xb = x + b * 3072;
    for (int j = t; j < 3072; j += 288) xs[j] = xb[j];
    for (int j = t; j < 486; j += 288) {
        int hcap = j / 243, r = j % 243;
        ws[hcap][r] = w[(oc0 + hcap * 128) * 243 + r];
    }
    __syncthreads();
    int halfsel = t / 144;
    int tt = t % 144;
    int oc = oc0 + halfsel * 128;
    int oy = tt / 6, ox0 = (tt % 6) * 4;
    float bv = bias[oc];
    float a0 = bv, a1 = bv, a2 = bv, a3 = bv;
#pragma unroll
    for (int ci = 0; ci < 3; ci++) {
#pragma unroll
        for (int ky = 0; ky < 9; ky++) {
            const float* xr = xs + ci * 1024 + (oy + ky) * 32 + ox0;
            float xv[12];
#pragma unroll
            for (int j = 0; j < 12; j++) xv[j] = xr[j];
            const float* wr = ws[halfsel] + ci * 81 + ky * 9;
#pragma unroll
            for (int kx = 0; kx < 9; kx++) {
                float wv = wr[kx];
                a0 = fmaf(wv, xv[kx], a0);
                a1 = fmaf(wv, xv[kx + 1], a1);
                a2 = fmaf(wv, xv[kx + 2], a2);
                a3 = fmaf(wv, xv[kx + 3], a3);
            }
        }
    }
    float* hp = g_h + (((size_t)b * 256 + oc) * 24 + oy) * 24 + ox0;
    hp[0] = fmaxf(a0, 0.f); hp[1] = fmaxf(a1, 0.f);
    hp[2] = fmaxf(a2, 0.f); hp[3] = fmaxf(a3, 0.f);
}

// ---------------- init p with bias ------------------------------------------
__global__ void pinit_k(const float* __restrict__ pb) {
    int i = blockIdx.x * 256 + threadIdx.x;
    if (i < GM * 128) g_p[i] = pb[i & 127];
}

// ---------------- primary-caps conv as GEMM ---------------------------------
// M=5184 (b*81+s), N=128 (oc), K=16384 (c*64+kh*8+kw). BM=BN=128, BK=8.
// grid (41 m-tiles, 16 k-splits), block 256, thread tile 8x8 with f32x2 accum.
// A gathered from g_h (implicit im2col), atomicAdd epilogue into g_p.
__global__ void __launch_bounds__(256) gemm_k(const float* __restrict__ wgt) {
    __shared__ __align__(16) float As[8][128];
    __shared__ __align__(16) float Bs[8][128];
    int t = threadIdx.x;
    int m0 = blockIdx.x * 128;
    int k0b = blockIdx.y * 1024;
    int row = t >> 1, half = t & 1;
    int ml = m0 + row;
    bool mv = ml < GM;
    int bb = mv ? ml / 81 : 0;
    int s  = mv ? ml % 81 : 0;
    const float* hb = g_h + (size_t)bb * 147456 + (2 * (s / 9)) * 24 + 2 * (s % 9);
    const float* wb = wgt + (size_t)row * 16384 + half * 4;
    int tx = t & 15, ty = t >> 4;
    unsigned long long acc[8][4];
#pragma unroll
    for (int i = 0; i < 8; i++)
#pragma unroll
        for (int j = 0; j < 4; j++) acc[i][j] = 0ull;

    for (int it = 0; it < 128; it++) {
        int k0 = k0b + it * 8;
        int c = k0 >> 6, kh = (k0 >> 3) & 7;
        float2 va = make_float2(0.f, 0.f), vb = make_float2(0.f, 0.f);
        if (mv) {
            const float2* ap = (const float2*)(hb + c * 576 + kh * 24 + half * 4);
            va = ap[0]; vb = ap[1];
        }
        float4 bw = *(const float4*)(wb + k0);
        As[half * 4 + 0][row] = va.x; As[half * 4 + 1][row] = va.y;
        As[half * 4 + 2][row] = vb.x; As[half * 4 + 3][row] = vb.y;
        Bs[half * 4 + 0][row] = bw.x; Bs[half * 4 + 1][row] = bw.y;
        Bs[half * 4 + 2][row] = bw.z; Bs[half * 4 + 3][row] = bw.w;
        __syncthreads();
#pragma unroll
        for (int kk = 0; kk < 8; kk++) {
            float af[8];
            *(float4*)&af[0] = *(const float4*)&As[kk][ty * 8];
            *(float4*)&af[4] = *(const float4*)&As[kk][ty * 8 + 4];
            unsigned long long ad[8];
#pragma unroll
            for (int i = 0; i < 8; i++) ad[i] = pk2(af[i]);
            const unsigned long long* bp = (const unsigned long long*)&Bs[kk][tx * 8];
            unsigned long long b0 = bp[0], b1 = bp[1], b2 = bp[2], b3 = bp[3];
#pragma unroll
            for (int i = 0; i < 8; i++) {
                fma2(acc[i][0], ad[i], b0);
                fma2(acc[i][1], ad[i], b1);
                fma2(acc[i][2], ad[i], b2);
                fma2(acc[i][3], ad[i], b3);
            }
        }
        __syncthreads();
    }
#pragma unroll
    for (int i = 0; i < 8; i++) {
        int m = m0 + ty * 8 + i;
        if (m < GM) {
            float* pp = g_p + (size_t)m * 128 + tx * 8;
#pragma unroll
            for (int j = 0; j < 4; j++) {
                float lo = __uint_as_float((unsigned)(acc[i][j] & 0xffffffffull));
                float hi = __uint_as_float((unsigned)(acc[i][j] >> 32));
                atomicAdd(pp + 2 * j, lo);
                atomicAdd(pp + 2 * j + 1, hi);
            }
        }
    }
}

// ---------------- squash primary caps → u -----------------------------------
__global__ void squashu_k() {
    int idx = blockIdx.x * 256 + threadIdx.x;
    if (idx >= BATCH * NODES) return;
    int b = idx / NODES, node = idx % NODES;
    int d = node / 81, sp = node % 81;
    const float* pp = g_p + (size_t)(b * 81 + sp) * 128 + d;
    float v[8], sn = 0.f;
#pragma unroll
    for (int i = 0; i < 8; i++) { v[i] = pp[i * 16]; sn = fmaf(v[i], v[i], sn); }
    float sc = sn / ((1.f + sn) * sqrtf(sn));
    float* up = g_u + (size_t)idx * 8;
#pragma unroll
    for (int i = 0; i < 8; i++) up[i] = v[i] * sc;
}

// ---------------- priors = einsum('bni,ncio->bnco') -------------------------
// grid 324 blocks x 4 nodes each; route_w[n] (43x8x16) cached in smem,
// per-thread weight registers, loop over batch. Write-bound (228MB).
__global__ void __launch_bounds__(256) priors_k(const float* __restrict__ rw) {
    __shared__ float ws[5504];
    __shared__ __align__(16) float us[512];
    int t = threadIdx.x;
    for (int nn = 0; nn < 4; nn++) {
        int n = blockIdx.x * 4 + nn;
        const float* rwn = rw + (size_t)n * 5504;
        for (int j = t; j < 5504; j += 256) ws[j] = rwn[j];
        for (int j = t; j < 512; j += 256)
            us[j] = g_u[((size_t)(j >> 3) * NODES + n) * 8 + (j & 7)];
        __syncthreads();
        int i0 = t, i1 = t + 256, i2 = t + 512;
        float w0[8], w1[8], w2[8];
#pragma unroll
        for (int i = 0; i < 8; i++) {
            w0[i] = ws[((i0 >> 4) * 8 + i) * 16 + (i0 & 15)];
            w1[i] = ws[((i1 >> 4) * 8 + i) * 16 + (i1 & 15)];
            w2[i] = (i2 < CO) ? ws[((i2 >> 4) * 8 + i) * 16 + (i2 & 15)] : 0.f;
        }
        for (int b = 0; b < 64; b++) {
            float4 ua = *(const float4*)&us[b * 8];
            float4 ub = *(const float4*)&us[b * 8 + 4];
            float u8[8] = {ua.x, ua.y, ua.z, ua.w, ub.x, ub.y, ub.z, ub.w};
            float r0 = 0.f, r1 = 0.f, r2 = 0.f;
#pragma unroll
            for (int i = 0; i < 8; i++) {
                r0 = fmaf(w0[i], u8[i], r0);
                r1 = fmaf(w1[i], u8[i], r1);
                r2 = fmaf(w2[i], u8[i], r2);
            }
            float* dst = g_pr + ((size_t)b * NODES + n) * CO;
            dst[i0] = r0; dst[i1] = r1;
            if (i2 < CO) dst[i2] = r2;
        }
        __syncthreads();
    }
}

// ---------------- fused routing pass ----------------------------------------
// pass k: delta_{k-1} (from outputs_{k-1}) + logit update + softmax over 43
// classes + accumulate s_k. One priors read per pass. grid (64, 8), block 704.
__global__ void __launch_bounds__(704) pass_k(int iter) {
    __shared__ float arr[NC];
    __shared__ float prb[NC];
    int t = threadIdx.x;
    bool act = t < CO;
    int c = t >> 4, o = t & 15;
    int b = blockIdx.x;
    int n0 = blockIdx.y * 162;
    float outreg = (iter > 0 && act) ? g_o[b * CO + t] : 0.f;
    float sacc = 0.f;
    const float* prbase = g_pr + (size_t)b * NODES * CO;
    for (int n = n0; n < n0 + 162; n++) {
        float pr = act ? prbase[(size_t)n * CO + t] : 0.f;
        if (iter > 0) {
            float d = pr * outreg;
            d += __shfl_xor_sync(0xffffffffu, d, 8, 16);
            d += __shfl_xor_sync(0xffffffffu, d, 4, 16);
            d += __shfl_xor_sync(0xffffffffu, d, 2, 16);
            d += __shfl_xor_sync(0xffffffffu, d, 1, 16);
            if (act && o == 0) {
                int li = (b * NODES + n) * NC + c;
                float l;
                if (iter == 1) { l = d; g_lg[li] = d; }
                else           { l = g_lg[li] + d; }
                arr[c] = l;
            }
            __syncthreads();
            if (t < 32) {
                float v1 = (t < NC) ? arr[t] : -3.4e38f;
                float v2 = (t + 32 < NC) ? arr[t + 32] : -3.4e38f;
                float m = fmaxf(v1, v2);
#pragma unroll
                for (int off = 16; off >= 1; off >>= 1)
                    m = fmaxf(m, __shfl_xor_sync(0xffffffffu, m, off));
                float e1 = (t < NC) ? expf(v1 - m) : 0.f;
                float e2 = (t + 32 < NC) ? expf(v2 - m) : 0.f;
                float ss = e1 + e2;
#pragma unroll
                for (int off = 16; off >= 1; off >>= 1)
                    ss += __shfl_xor_sync(0xffffffffu, ss, off);
                float inv = 1.f / ss;
                if (t < NC) prb[t] = e1 * inv;
                if (t + 32 < NC) prb[t + 32] = e2 * inv;
            }
            __syncthreads();
            if (act) sacc = fmaf(prb[c], pr, sacc);
        } else {
            sacc += pr;
        }
    }
    if (act) atomicAdd(&g_s[b * CO + t], iter == 0 ? sacc * (1.f / 43.f) : sacc);
}

// ---------------- squash s → outputs (or final scores) ----------------------
// Also re-zeroes g_s so the graph replays identically.
__global__ void __launch_bounds__(704) sqout_k(int final_it, float* __restrict__ outp) {
    int t = threadIdx.x, b = blockIdx.x;
    bool act = t < CO;
    int c = t >> 4, o = t & 15;
    float v = act ? g_s[b * CO + t] : 0.f;
    float q = v * v;
    q += __shfl_xor_sync(0xffffffffu, q, 8, 16);
    q += __shfl_xor_sync(0xffffffffu, q, 4, 16);
    q += __shfl_xor_sync(0xffffffffu, q, 2, 16);
    q += __shfl_xor_sync(0xffffffffu, q, 1, 16);
    if (final_it) {
        if (act && o == 0) outp[b * NC + c] = q / (1.f + q);
    } else {
        if (act) g_o[b * CO + t] = v * (q / ((1.f + q) * sqrtf(q)));
    }
    if (act) g_s[b * CO + t] = 0.f;
}

// ---------------- launch ----------------------------------------------------
extern "C" void kernel_launch(void* const* d_in, const int* in_sizes, int n_in,
                              void* d_out, int out_size) {
    const float* x  = (const float*)d_in[0];
    const float* w1 = (const float*)d_in[1];
    const float* b1 = (const float*)d_in[2];
    const float* pw = (const float*)d_in[3];
    const float* pb = (const float*)d_in[4];
    const float* rw = (const float*)d_in[5];
    float* out = (float*)d_out;

    conv1_k<<<dim3(64, 128), 288>>>(x, w1, b1);
    pinit_k<<<(GM * 128 + 255) / 256, 256>>>(pb);
    gemm_k<<<dim3(41, 16), 256>>>(pw);
    squashu_k<<<(BATCH * NODES + 255) / 256, 256>>>();
    priors_k<<<324, 256>>>(rw);

    pass_k<<<dim3(64, 8), 704>>>(0);
    sqout_k<<<64, 704>>>(0, out);
    pass_k<<<dim3(64, 8), 704>>>(1);
    sqout_k<<<64, 704>>>(0, out);
    pass_k<<<dim3(64, 8), 704>>>(2);
    sqout_k<<<64, 704>>>(1, out);
}

// round 2
// speedup vs baseline: 1.1244x; 1.1244x over previous
#include <cuda_runtime.h>

#define BATCH 64
#define GM 5184            // 64*81 patches
#define KTOT 16384         // 256*8*8
#define NODES 1296
#define NC 43
#define OD 16
#define CO 688             // 43*16

// ---------------- scratch (static device globals; zero-initialized) ----------
__device__ float g_h[BATCH*256*24*24];        // conv1 output
__device__ float g_p[GM*128];                 // prim conv output [m][oc]
__device__ float g_u[BATCH*NODES*8];          // squashed prim caps
__device__ float g_pr[57065472];              // priors [b][n][c][o] (228MB)
__device__ float g_lg[BATCH*NODES*NC];        // routing logits
__device__ float g_s[BATCH*CO];               // routing sum (zeroed by sqout)
__device__ float g_o[BATCH*CO];               // routing outputs

// ---------------- f32x2 helpers ---------------------------------------------
__device__ __forceinline__ void fma2(unsigned long long& d,
                                     unsigned long long a, unsigned long long b) {
    asm("fma.rn.f32x2 %0, %1, %2, %0;" : "+l"(d) : "l"(a), "l"(b));
}

// ---------------- conv1 + relu ----------------------------------------------
// grid (64 batch, 128 oc-pairs), block 288 = 2 halves x 144 threads.
__global__ void __launch_bounds__(288) conv1_k(const float* __restrict__ x,
                                               const float* __restrict__ w,
                                               const float* __restrict__ bias) {
    __shared__ float xs[3072];
    __shared__ float ws[2][243];
    int b = blockIdx.x, oc0 = blockIdx.y, t = threadIdx.x;
    const float* xb = x + b * 3072;
    for (int j = t; j < 3072; j += 288) xs[j] = xb[j];
    for (int j = t; j < 486; j += 288) {
        int hcap = j / 243, r = j % 243;
        ws[hcap][r] = w[(oc0 + hcap * 128) * 243 + r];
    }
    __syncthreads();
    int halfsel = t / 144;
    int tt = t % 144;
    int oc = oc0 + halfsel * 128;
    int oy = tt / 6, ox0 = (tt % 6) * 4;
    float bv = bias[oc];
    float a0 = bv, a1 = bv, a2 = bv, a3 = bv;
#pragma unroll
    for (int ci = 0; ci < 3; ci++) {
#pragma unroll
        for (int ky = 0; ky < 9; ky++) {
            const float* xr = xs + ci * 1024 + (oy + ky) * 32 + ox0;
            float xv[12];
#pragma unroll
            for (int j = 0; j < 12; j++) xv[j] = xr[j];
            const float* wr = ws[halfsel] + ci * 81 + ky * 9;
#pragma unroll
            for (int kx = 0; kx < 9; kx++) {
                float wv = wr[kx];
                a0 = fmaf(wv, xv[kx], a0);
                a1 = fmaf(wv, xv[kx + 1], a1);
                a2 = fmaf(wv, xv[kx + 2], a2);
                a3 = fmaf(wv, xv[kx + 3], a3);
            }
        }
    }
    float* hp = g_h + (((size_t)b * 256 + oc) * 24 + oy) * 24 + ox0;
    hp[0] = fmaxf(a0, 0.f); hp[1] = fmaxf(a1, 0.f);
    hp[2] = fmaxf(a2, 0.f); hp[3] = fmaxf(a3, 0.f);
}

// ---------------- init p with bias ------------------------------------------
__global__ void pinit_k(const float* __restrict__ pb) {
    int i = blockIdx.x * 256 + threadIdx.x;
    if (i < GM * 128) g_p[i] = pb[i & 127];
}

// ---------------- primary-caps conv as GEMM ---------------------------------
// M=5184, N=128, K=16384. BM=BN=128, BK=8, split-K 16.
// Double-buffered smem, A stored duplicated so f32x2 operands are one LDS.64.
__global__ void __launch_bounds__(256) gemm_k(const float* __restrict__ wgt) {
    __shared__ __align__(16) float As[2][8][256];   // duplicated pairs
    __shared__ __align__(16) float Bs[2][8][128];
    int t = threadIdx.x;
    int m0 = blockIdx.x * 128;
    int k0b = blockIdx.y * 1024;
    int row = t >> 1, half = t & 1;
    int ml = m0 + row;
    bool mv = ml < GM;
    int bb = mv ? ml / 81 : 0;
    int s  = mv ? ml % 81 : 0;
    const float* hb = g_h + (size_t)bb * 147456 + (2 * (s / 9)) * 24 + 2 * (s % 9);
    const float* wb = wgt + (size_t)row * 16384 + half * 4;
    int tx = t & 15, ty = t >> 4;
    unsigned long long acc[8][4];
#pragma unroll
    for (int i = 0; i < 8; i++)
#pragma unroll
        for (int j = 0; j < 4; j++) acc[i][j] = 0ull;

    // prologue: load tile 0
    float2 va, vb; float4 bw;
    {
        int k0 = k0b;
        int c = k0 >> 6, kh = (k0 >> 3) & 7;
        va = make_float2(0.f, 0.f); vb = make_float2(0.f, 0.f);
        if (mv) {
            const float2* ap = (const float2*)(hb + c * 576 + kh * 24 + half * 4);
            va = ap[0]; vb = ap[1];
        }
        bw = *(const float4*)(wb + k0);
        float2* a0 = (float2*)&As[0][half * 4 + 0][2 * row];
        float2* a1 = (float2*)&As[0][half * 4 + 1][2 * row];
        float2* a2 = (float2*)&As[0][half * 4 + 2][2 * row];
        float2* a3 = (float2*)&As[0][half * 4 + 3][2 * row];
        *a0 = make_float2(va.x, va.x); *a1 = make_float2(va.y, va.y);
        *a2 = make_float2(vb.x, vb.x); *a3 = make_float2(vb.y, vb.y);
        Bs[0][half * 4 + 0][row] = bw.x; Bs[0][half * 4 + 1][row] = bw.y;
        Bs[0][half * 4 + 2][row] = bw.z; Bs[0][half * 4 + 3][row] = bw.w;
    }
    __syncthreads();

    for (int it = 0; it < 128; it++) {
        int buf = it & 1;
        // issue loads for next tile (overlap with compute)
        if (it + 1 < 128) {
            int k0 = k0b + (it + 1) * 8;
            int c = k0 >> 6, kh = (k0 >> 3) & 7;
            va = make_float2(0.f, 0.f); vb = make_float2(0.f, 0.f);
            if (mv) {
                const float2* ap = (const float2*)(hb + c * 576 + kh * 24 + half * 4);
                va = ap[0]; vb = ap[1];
            }
            bw = *(const float4*)(wb + k0);
        }
#pragma unroll
        for (int kk = 0; kk < 8; kk++) {
            unsigned long long ad[8];
#pragma unroll
            for (int i = 0; i < 8; i++)
                ad[i] = *(const unsigned long long*)&As[buf][kk][2 * (ty * 8 + i)];
            const unsigned long long* bp = (const unsigned long long*)&Bs[buf][kk][tx * 8];
            unsigned long long b0 = bp[0], b1 = bp[1], b2 = bp[2], b3 = bp[3];
#pragma unroll
            for (int i = 0; i < 8; i++) {
                fma2(acc[i][0], ad[i], b0);
                fma2(acc[i][1], ad[i], b1);
                fma2(acc[i][2], ad[i], b2);
                fma2(acc[i][3], ad[i], b3);
            }
        }
        if (it + 1 < 128) {
            int nb = buf ^ 1;
            float2* a0 = (float2*)&As[nb][half * 4 + 0][2 * row];
            float2* a1 = (float2*)&As[nb][half * 4 + 1][2 * row];
            float2* a2 = (float2*)&As[nb][half * 4 + 2][2 * row];
            float2* a3 = (float2*)&As[nb][half * 4 + 3][2 * row];
            *a0 = make_float2(va.x, va.x); *a1 = make_float2(va.y, va.y);
            *a2 = make_float2(vb.x, vb.x); *a3 = make_float2(vb.y, vb.y);
            Bs[nb][half * 4 + 0][row] = bw.x; Bs[nb][half * 4 + 1][row] = bw.y;
            Bs[nb][half * 4 + 2][row] = bw.z; Bs[nb][half * 4 + 3][row] = bw.w;
        }
        __syncthreads();
    }
#pragma unroll
    for (int i = 0; i < 8; i++) {
        int m = m0 + ty * 8 + i;
        if (m < GM) {
            float* pp = g_p + (size_t)m * 128 + tx * 8;
#pragma unroll
            for (int j = 0; j < 4; j++) {
                float lo = __uint_as_float((unsigned)(acc[i][j] & 0xffffffffull));
                float hi = __uint_as_float((unsigned)(acc[i][j] >> 32));
                atomicAdd(pp + 2 * j, lo);
                atomicAdd(pp + 2 * j + 1, hi);
            }
        }
    }
}

// ---------------- squash primary caps → u -----------------------------------
__global__ void squashu_k() {
    int idx = blockIdx.x * 256 + threadIdx.x;
    if (idx >= BATCH * NODES) return;
    int b = idx / NODES, node = idx % NODES;
    int d = node / 81, sp = node % 81;
    const float* pp = g_p + (size_t)(b * 81 + sp) * 128 + d;
    float v[8], sn = 0.f;
#pragma unroll
    for (int i = 0; i < 8; i++) { v[i] = pp[i * 16]; sn = fmaf(v[i], v[i], sn); }
    float sc = sn / ((1.f + sn) * sqrtf(sn));
    float* up = g_u + (size_t)idx * 8;
#pragma unroll
    for (int i = 0; i < 8; i++) up[i] = v[i] * sc;
}

// ---------------- priors = einsum('bni,ncio->bnco') -------------------------
__global__ void __launch_bounds__(256) priors_k(const float* __restrict__ rw) {
    __shared__ float ws[5504];
    __shared__ __align__(16) float us[512];
    int t = threadIdx.x;
    for (int nn = 0; nn < 4; nn++) {
        int n = blockIdx.x * 4 + nn;
        const float* rwn = rw + (size_t)n * 5504;
        for (int j = t; j < 5504; j += 256) ws[j] = rwn[j];
        for (int j = t; j < 512; j += 256)
            us[j] = g_u[((size_t)(j >> 3) * NODES + n) * 8 + (j & 7)];
        __syncthreads();
        int i0 = t, i1 = t + 256, i2 = t + 512;
        float w0[8], w1[8], w2[8];
#pragma unroll
        for (int i = 0; i < 8; i++) {
            w0[i] = ws[((i0 >> 4) * 8 + i) * 16 + (i0 & 15)];
            w1[i] = ws[((i1 >> 4) * 8 + i) * 16 + (i1 & 15)];
            w2[i] = (i2 < CO) ? ws[((i2 >> 4) * 8 + i) * 16 + (i2 & 15)] : 0.f;
        }
        for (int b = 0; b < 64; b++) {
            float4 ua = *(const float4*)&us[b * 8];
            float4 ub = *(const float4*)&us[b * 8 + 4];
            float u8[8] = {ua.x, ua.y, ua.z, ua.w, ub.x, ub.y, ub.z, ub.w};
            float r0 = 0.f, r1 = 0.f, r2 = 0.f;
#pragma unroll
            for (int i = 0; i < 8; i++) {
                r0 = fmaf(w0[i], u8[i], r0);
                r1 = fmaf(w1[i], u8[i], r1);
                r2 = fmaf(w2[i], u8[i], r2);
            }
            float* dst = g_pr + ((size_t)b * NODES + n) * CO;
            dst[i0] = r0; dst[i1] = r1;
            if (i2 < CO) dst[i2] = r2;
        }
        __syncthreads();
    }
}

// ---------------- fused routing pass ----------------------------------------
// grid (64 b, 48 node-groups), 27 nodes per block, register prefetch of the
// next node's priors row so the DRAM latency overlaps the softmax barriers.
__global__ void __launch_bounds__(704) pass_k(int iter) {
    __shared__ float arr[NC];
    __shared__ float prb[NC];
    int t = threadIdx.x;
    bool act = t < CO;
    int c = t >> 4, o = t & 15;
    int b = blockIdx.x;
    int n0 = blockIdx.y * 27;
    int nend = n0 + 27;
    float outreg = (iter > 0 && act) ? g_o[b * CO + t] : 0.f;
    float sacc = 0.f;
    const float* prbase = g_pr + (size_t)b * NODES * CO;
    float cur = act ? prbase[(size_t)n0 * CO + t] : 0.f;
    for (int n = n0; n < nend; n++) {
        float nxt = (act && n + 1 < nend) ? prbase[(size_t)(n + 1) * CO + t] : 0.f;
        if (iter > 0) {
            float d = cur * outreg;
            d += __shfl_xor_sync(0xffffffffu, d, 8, 16);
            d += __shfl_xor_sync(0xffffffffu, d, 4, 16);
            d += __shfl_xor_sync(0xffffffffu, d, 2, 16);
            d += __shfl_xor_sync(0xffffffffu, d, 1, 16);
            if (act && o == 0) {
                int li = (b * NODES + n) * NC + c;
                float l;
                if (iter == 1) { l = d; g_lg[li] = d; }
                else           { l = g_lg[li] + d; }
                arr[c] = l;
            }
            __syncthreads();
            if (t < 32) {
                float v1 = (t < NC) ? arr[t] : -3.4e38f;
                float v2 = (t + 32 < NC) ? arr[t + 32] : -3.4e38f;
                float m = fmaxf(v1, v2);
#pragma unroll
                for (int off = 16; off >= 1; off >>= 1)
                    m = fmaxf(m, __shfl_xor_sync(0xffffffffu, m, off));
                float e1 = (t < NC) ? expf(v1 - m) : 0.f;
                float e2 = (t + 32 < NC) ? expf(v2 - m) : 0.f;
                float ss = e1 + e2;
#pragma unroll
                for (int off = 16; off >= 1; off >>= 1)
                    ss += __shfl_xor_sync(0xffffffffu, ss, off);
                float inv = 1.f / ss;
                if (t < NC) prb[t] = e1 * inv;
                if (t + 32 < NC) prb[t + 32] = e2 * inv;
            }
            __syncthreads();
            if (act) sacc = fmaf(prb[c], cur, sacc);
            __syncthreads();
        } else {
            sacc += cur;
        }
        cur = nxt;
    }
    if (act) atomicAdd(&g_s[b * CO + t], iter == 0 ? sacc * (1.f / 43.f) : sacc);
}

// ---------------- squash s → outputs (or final scores) ----------------------
__global__ void __launch_bounds__(704) sqout_k(int final_it, float* __restrict__ outp) {
    int t = threadIdx.x, b = blockIdx.x;
    bool act = t < CO;
    int c = t >> 4, o = t & 15;
    float v = act ? g_s[b * CO + t] : 0.f;
    float q = v * v;
    q += __shfl_xor_sync(0xffffffffu, q, 8, 16);
    q += __shfl_xor_sync(0xffffffffu, q, 4, 16);
    q += __shfl_xor_sync(0xffffffffu, q, 2, 16);
    q += __shfl_xor_sync(0xffffffffu, q, 1, 16);
    if (final_it) {
        if (act && o == 0) outp[b * NC + c] = q / (1.f + q);
    } else {
        if (act) g_o[b * CO + t] = v * (q / ((1.f + q) * sqrtf(q)));
    }
    if (act) g_s[b * CO + t] = 0.f;
}

// ---------------- launch ----------------------------------------------------
extern "C" void kernel_launch(void* const* d_in, const int* in_sizes, int n_in,
                              void* d_out, int out_size) {
    const float* x  = (const float*)d_in[0];
    const float* w1 = (const float*)d_in[1];
    const float* b1 = (const float*)d_in[2];
    const float* pw = (const float*)d_in[3];
    const float* pb = (const float*)d_in[4];
    const float* rw = (const float*)d_in[5];
    float* out = (float*)d_out;

    conv1_k<<<dim3(64, 128), 288>>>(x, w1, b1);
    pinit_k<<<(GM * 128 + 255) / 256, 256>>>(pb);
    gemm_k<<<dim3(41, 16), 256>>>(pw);
    squashu_k<<<(BATCH * NODES + 255) / 256, 256>>>();
    priors_k<<<324, 256>>>(rw);

    pass_k<<<dim3(64, 48), 704>>>(0);
    sqout_k<<<64, 704>>>(0, out);
    pass_k<<<dim3(64, 48), 704>>>(1);
    sqout_k<<<64, 704>>>(0, out);
    pass_k<<<dim3(64, 48), 704>>>(2);
    sqout_k<<<64, 704>>>(1, out);
}